// round 16
// baseline (speedup 1.0000x reference)
#include <cuda_runtime.h>
#include <cuda_bf16.h>
#include <math.h>
#include <stdint.h>

#define BB   2
#define SS   2048
#define DD   1024
#define HH   16
#define HD   64
#define BHN  (BB*HH)       // 32
#define MTOK (BB*SS)       // 4096

// ---- static scratch (allocation-free rule: __device__ globals) ----
__device__ float g_tmp[(size_t)MTOK*DD];          // projection temp [B,S,D]
__device__ float g_ctx[(size_t)MTOK*DD];          // merged-head context
__device__ float g_attn[(size_t)BHN*SS*SS];       // fallback attn
__device__ __nv_bfloat16 g_Ahi[(size_t)MTOK*DD];  // activation split
__device__ __nv_bfloat16 g_Alo[(size_t)MTOK*DD];
__device__ __nv_bfloat16 g_Whi[(size_t)DD*DD];    // weight split
__device__ __nv_bfloat16 g_Wlo[(size_t)DD*DD];
__device__ __nv_bfloat16 g_Qh[(size_t)BHN*SS*HD]; // normalized Q/K split
__device__ __nv_bfloat16 g_Ql[(size_t)BHN*SS*HD];
__device__ __nv_bfloat16 g_Kh[(size_t)BHN*SS*HD];
__device__ __nv_bfloat16 g_Kl[(size_t)BHN*SS*HD];
__device__ __nv_bfloat16 g_Vh[(size_t)BHN*SS*HD]; // V split heads bf16 hi/lo
__device__ __nv_bfloat16 g_Vl[(size_t)BHN*SS*HD];

// ============================================================
// helpers
// ============================================================
__device__ __forceinline__ uint32_t smem_u32(const void* p) {
    return (uint32_t)__cvta_generic_to_shared(p);
}
__device__ __forceinline__ void cp16(uint32_t dst, const void* src) {
    asm volatile("cp.async.ca.shared.global [%0], [%1], 16;" :: "r"(dst), "l"(src));
}
#define CP_COMMIT() asm volatile("cp.async.commit_group;")
#define CP_WAIT(n)  asm volatile("cp.async.wait_group %0;" :: "n"(n))

__device__ __forceinline__ void ldsm4(uint32_t* r, uint32_t a) {
    asm volatile("ldmatrix.sync.aligned.m8n8.x4.shared.b16 {%0,%1,%2,%3}, [%4];"
        : "=r"(r[0]), "=r"(r[1]), "=r"(r[2]), "=r"(r[3]) : "r"(a));
}
// non-transposed x2: B stored [n][k] (contiguous k) for mma.row.col
__device__ __forceinline__ void ldsm2(uint32_t* r, uint32_t a) {
    asm volatile("ldmatrix.sync.aligned.m8n8.x2.shared.b16 {%0,%1}, [%2];"
        : "=r"(r[0]), "=r"(r[1]) : "r"(a));
}
// transposed x2: B stored [k][n] (contiguous n)
__device__ __forceinline__ void ldsm2t(uint32_t* r, uint32_t a) {
    asm volatile("ldmatrix.sync.aligned.m8n8.x2.trans.shared.b16 {%0,%1}, [%2];"
        : "=r"(r[0]), "=r"(r[1]) : "r"(a));
}
__device__ __forceinline__ void mma_bf16(float* c, const uint32_t* a, const uint32_t* b) {
    asm volatile(
        "mma.sync.aligned.m16n8k16.row.col.f32.bf16.bf16.f32 "
        "{%0,%1,%2,%3}, {%4,%5,%6,%7}, {%8,%9}, {%0,%1,%2,%3};"
        : "+f"(c[0]), "+f"(c[1]), "+f"(c[2]), "+f"(c[3])
        : "r"(a[0]), "r"(a[1]), "r"(a[2]), "r"(a[3]), "r"(b[0]), "r"(b[1]));
}

// swizzled smem offset for [row][chunk-of-16B] tiles (row stride 32B)
__device__ __forceinline__ uint32_t swz_off(int row, int chunk) {
    return (uint32_t)(row * 32 + ((chunk ^ ((row >> 2) & 1)) << 4));
}
// swizzled offset for 128B-row tiles: [k-row][8 chunks of 16B]
__device__ __forceinline__ uint32_t swzB(int k, int chunk) {
    return (uint32_t)(k * 128 + ((chunk ^ (k & 7)) << 4));
}

__device__ __forceinline__ uint32_t bf2pack(float a, float b) {
    __nv_bfloat162 t;
    t.x = __float2bfloat16_rn(a);
    t.y = __float2bfloat16_rn(b);
    return *(uint32_t*)&t;
}

// ============================================================
// fp32 -> bf16 hi/lo split
// ============================================================
__global__ __launch_bounds__(256) void cvt_split_kernel(
    const float4* __restrict__ x, uint2* __restrict__ hi, uint2* __restrict__ lo, int n4)
{
    int i = blockIdx.x * 256 + threadIdx.x;
    if (i >= n4) return;
    float4 v = x[i];
    __nv_bfloat16 hx = __float2bfloat16_rn(v.x);
    __nv_bfloat16 hy = __float2bfloat16_rn(v.y);
    __nv_bfloat16 hz = __float2bfloat16_rn(v.z);
    __nv_bfloat16 hw = __float2bfloat16_rn(v.w);
    uint2 h, l;
    { __nv_bfloat162 t; t.x = hx; t.y = hy; h.x = *(uint32_t*)&t; }
    { __nv_bfloat162 t; t.x = hz; t.y = hw; h.y = *(uint32_t*)&t; }
    l.x = bf2pack(v.x - __bfloat162float(hx), v.y - __bfloat162float(hy));
    l.y = bf2pack(v.z - __bfloat162float(hz), v.w - __bfloat162float(hw));
    hi[i] = h;
    lo[i] = l;
}

// ============================================================
// shared GEMM machinery: 128x128 tile, 8 warps (2m x 4n), k-step 16
// ============================================================
__device__ __forceinline__ void load_stage(
    uint32_t saH, uint32_t saL, uint32_t sbH, uint32_t sbL,
    const __nv_bfloat16* Ah, const __nv_bfloat16* Al,
    const __nv_bfloat16* Bh, const __nv_bfloat16* Bl,
    int K, int k0, int tid)
{
    int row = tid >> 1, ch = tid & 1;
    uint32_t off = swz_off(row, ch);
    size_t g = (size_t)row * K + k0 + ch * 8;
    cp16(saH + off, Ah + g);
    cp16(saL + off, Al + g);
    cp16(sbH + off, Bh + g);
    cp16(sbL + off, Bl + g);
}

__device__ __forceinline__ void compute_step(
    uint32_t saH, uint32_t saL, uint32_t sbH, uint32_t sbL,
    int wm, int wn, int lane, float c[4][4][4])
{
    uint32_t ah[4][4], al[4][4], bh[4][2], bl[4][2];
    int r = lane & 15, kc = lane >> 4;
#pragma unroll
    for (int fm = 0; fm < 4; fm++) {
        int row = wm * 64 + fm * 16 + r;
        uint32_t off = swz_off(row, kc);
        ldsm4(ah[fm], saH + off);
        ldsm4(al[fm], saL + off);
    }
    int rb = lane & 7, kb = (lane >> 3) & 1;
#pragma unroll
    for (int fn = 0; fn < 4; fn++) {
        int row = wn * 32 + fn * 8 + rb;
        uint32_t off = swz_off(row, kb);
        ldsm2(bh[fn], sbH + off);   // B is [n][k]: NON-trans
        ldsm2(bl[fn], sbL + off);
    }
#pragma unroll
    for (int fm = 0; fm < 4; fm++)
#pragma unroll
        for (int fn = 0; fn < 4; fn++) {
            mma_bf16(c[fm][fn], ah[fm], bh[fn]);
            mma_bf16(c[fm][fn], ah[fm], bl[fn]);
            mma_bf16(c[fm][fn], al[fm], bh[fn]);
        }
}

// ============================================================
// projection GEMM: C[M,N] = A@W^T + bias (bf16-split inputs)
// ============================================================
__global__ __launch_bounds__(256) void gemm_bf16s_kernel(
    const __nv_bfloat16* __restrict__ Ah, const __nv_bfloat16* __restrict__ Al,
    const __nv_bfloat16* __restrict__ Wh, const __nv_bfloat16* __restrict__ Wl,
    const float* __restrict__ bias, float* __restrict__ C, int M, int N, int K)
{
    __shared__ __align__(16) __nv_bfloat16 sA[2][2][128 * 16];
    __shared__ __align__(16) __nv_bfloat16 sB[2][2][128 * 16];
    int tid = threadIdx.x, lane = tid & 31, w = tid >> 5;
    int wm = w >> 2, wn = w & 3;
    int m0 = blockIdx.y * 128, n0 = blockIdx.x * 128;
    const __nv_bfloat16* Ah_b = Ah + (size_t)m0 * K;
    const __nv_bfloat16* Al_b = Al + (size_t)m0 * K;
    const __nv_bfloat16* Wh_b = Wh + (size_t)n0 * K;
    const __nv_bfloat16* Wl_b = Wl + (size_t)n0 * K;

    uint32_t saH[2] = { smem_u32(sA[0][0]), smem_u32(sA[1][0]) };
    uint32_t saL[2] = { smem_u32(sA[0][1]), smem_u32(sA[1][1]) };
    uint32_t sbH[2] = { smem_u32(sB[0][0]), smem_u32(sB[1][0]) };
    uint32_t sbL[2] = { smem_u32(sB[0][1]), smem_u32(sB[1][1]) };

    float c[4][4][4];
#pragma unroll
    for (int i = 0; i < 4; i++)
#pragma unroll
        for (int j = 0; j < 4; j++)
#pragma unroll
            for (int k = 0; k < 4; k++) c[i][j][k] = 0.0f;

    const int NK = K / 16;
    load_stage(saH[0], saL[0], sbH[0], sbL[0], Ah_b, Al_b, Wh_b, Wl_b, K, 0, tid);
    CP_COMMIT();

#pragma unroll 1
    for (int ks = 0; ks < NK; ks++) {
        int stg = ks & 1;
        if (ks + 1 < NK) {
            load_stage(saH[stg ^ 1], saL[stg ^ 1], sbH[stg ^ 1], sbL[stg ^ 1],
                       Ah_b, Al_b, Wh_b, Wl_b, K, (ks + 1) * 16, tid);
            CP_COMMIT();
            CP_WAIT(1);
        } else {
            CP_WAIT(0);
        }
        __syncthreads();
        compute_step(saH[stg], saL[stg], sbH[stg], sbL[stg], wm, wn, lane, c);
        __syncthreads();
    }

    int r0 = lane >> 2, cc = (lane & 3) << 1;
#pragma unroll
    for (int fn = 0; fn < 4; fn++) {
        int gcol = n0 + wn * 32 + fn * 8 + cc;
        float2 bb = *(const float2*)(bias + gcol);
#pragma unroll
        for (int fm = 0; fm < 4; fm++) {
            int gr = m0 + wm * 64 + fm * 16 + r0;
            float2 v0 = { c[fm][fn][0] + bb.x, c[fm][fn][1] + bb.y };
            float2 v1 = { c[fm][fn][2] + bb.x, c[fm][fn][3] + bb.y };
            *(float2*)(C + (size_t)gr * N + gcol) = v0;
            *(float2*)(C + (size_t)(gr + 8) * N + gcol) = v1;
        }
    }
}

// ============================================================
// scores GEMM: attn = mask ? exp(scale*Qn@Kn^T) : 0, per (b,h)
// (max-free softmax: |score| <= scale ~= 11.97 since Qn,Kn unit vectors,
//  so exp never overflows; masked lanes contribute exactly 0)
// ============================================================
__global__ __launch_bounds__(256) void scores_mma_kernel(
    const __nv_bfloat16* __restrict__ Qh, const __nv_bfloat16* __restrict__ Ql,
    const __nv_bfloat16* __restrict__ Kh, const __nv_bfloat16* __restrict__ Kl,
    const int* __restrict__ mask, const float* __restrict__ scale_p,
    float* __restrict__ attn)
{
    __shared__ __align__(16) __nv_bfloat16 sA[2][2][128 * 16];
    __shared__ __align__(16) __nv_bfloat16 sB[2][2][128 * 16];
    __shared__ int smask[128];
    int tid = threadIdx.x, lane = tid & 31, w = tid >> 5;
    int wm = w >> 2, wn = w & 3;
    int bh = blockIdx.z, b = bh >> 4;
    int q0 = blockIdx.y * 128, k0g = blockIdx.x * 128;
    const __nv_bfloat16* Ah_b = Qh + ((size_t)bh * SS + q0) * HD;
    const __nv_bfloat16* Al_b = Ql + ((size_t)bh * SS + q0) * HD;
    const __nv_bfloat16* Bh_b = Kh + ((size_t)bh * SS + k0g) * HD;
    const __nv_bfloat16* Bl_b = Kl + ((size_t)bh * SS + k0g) * HD;

    if (tid < 128) smask[tid] = mask[b * SS + k0g + tid];

    uint32_t saH[2] = { smem_u32(sA[0][0]), smem_u32(sA[1][0]) };
    uint32_t saL[2] = { smem_u32(sA[0][1]), smem_u32(sA[1][1]) };
    uint32_t sbH[2] = { smem_u32(sB[0][0]), smem_u32(sB[1][0]) };
    uint32_t sbL[2] = { smem_u32(sB[0][1]), smem_u32(sB[1][1]) };

    float c[4][4][4];
#pragma unroll
    for (int i = 0; i < 4; i++)
#pragma unroll
        for (int j = 0; j < 4; j++)
#pragma unroll
            for (int k = 0; k < 4; k++) c[i][j][k] = 0.0f;

    const int NK = HD / 16;  // 4
    load_stage(saH[0], saL[0], sbH[0], sbL[0], Ah_b, Al_b, Bh_b, Bl_b, HD, 0, tid);
    CP_COMMIT();

#pragma unroll 1
    for (int ks = 0; ks < NK; ks++) {
        int stg = ks & 1;
        if (ks + 1 < NK) {
            load_stage(saH[stg ^ 1], saL[stg ^ 1], sbH[stg ^ 1], sbL[stg ^ 1],
                       Ah_b, Al_b, Bh_b, Bl_b, HD, (ks + 1) * 16, tid);
            CP_COMMIT();
            CP_WAIT(1);
        } else {
            CP_WAIT(0);
        }
        __syncthreads();
        compute_step(saH[stg], saL[stg], sbH[stg], sbL[stg], wm, wn, lane, c);
        __syncthreads();
    }

    float scl = __ldg(scale_p);
    int r0 = lane >> 2, cc = (lane & 3) << 1;
#pragma unroll
    for (int fn = 0; fn < 4; fn++) {
        int lcol = wn * 32 + fn * 8 + cc;
        int m0v = smask[lcol], m1v = smask[lcol + 1];
        int gcol = k0g + lcol;
#pragma unroll
        for (int fm = 0; fm < 4; fm++) {
            int gq = q0 + wm * 64 + fm * 16 + r0;
            float2 v0, v1;
            v0.x = m0v ? __expf(scl * c[fm][fn][0]) : 0.0f;
            v0.y = m1v ? __expf(scl * c[fm][fn][1]) : 0.0f;
            v1.x = m0v ? __expf(scl * c[fm][fn][2]) : 0.0f;
            v1.y = m1v ? __expf(scl * c[fm][fn][3]) : 0.0f;
            *(float2*)(attn + ((size_t)bh * SS + gq) * SS + gcol) = v0;
            *(float2*)(attn + ((size_t)bh * SS + gq + 8) * SS + gcol) = v1;
        }
    }
}

// ============================================================
// Center-normalize + split into bf16 hi/lo [B,H,S,64]
// ============================================================
__global__ __launch_bounds__(256) void norm_split_bf16_kernel(
    const float* __restrict__ Y, __nv_bfloat16* __restrict__ hi,
    __nv_bfloat16* __restrict__ lo)
{
    int gw   = blockIdx.x * 8 + (threadIdx.x >> 5);
    int lane = threadIdx.x & 31;
    int h = gw & 15;
    int s = (gw >> 4) & (SS - 1);
    int b = gw >> 15;
    const float* src = Y + ((size_t)(b * SS + s)) * DD + h * HD;
    float x0 = src[lane], x1 = src[lane + 32];
    float sum = x0 + x1;
#pragma unroll
    for (int o = 16; o > 0; o >>= 1) sum += __shfl_xor_sync(0xffffffffu, sum, o);
    float mean = sum * (1.0f / 64.0f);
    x0 -= mean; x1 -= mean;
    float ss = x0 * x0 + x1 * x1;
#pragma unroll
    for (int o = 16; o > 0; o >>= 1) ss += __shfl_xor_sync(0xffffffffu, ss, o);
    float inv = 1.0f / fmaxf(sqrtf(ss), 1e-12f);
    x0 *= inv; x1 *= inv;
    size_t base = (((size_t)(b * HH + h)) * SS + s) * HD;
    __nv_bfloat16 h0 = __float2bfloat16_rn(x0);
    __nv_bfloat16 h1 = __float2bfloat16_rn(x1);
    hi[base + lane]      = h0;
    hi[base + lane + 32] = h1;
    lo[base + lane]      = __float2bfloat16_rn(x0 - __bfloat162float(h0));
    lo[base + lane + 32] = __float2bfloat16_rn(x1 - __bfloat162float(h1));
}

// V path: split heads + bf16 hi/lo split
__global__ __launch_bounds__(256) void split_v_bf16_kernel(
    const float* __restrict__ Y, __nv_bfloat16* __restrict__ hi,
    __nv_bfloat16* __restrict__ lo)
{
    int gw   = blockIdx.x * 8 + (threadIdx.x >> 5);
    int lane = threadIdx.x & 31;
    int h = gw & 15;
    int s = (gw >> 4) & (SS - 1);
    int b = gw >> 15;
    const float* src = Y + ((size_t)(b * SS + s)) * DD + h * HD;
    float x0 = src[lane], x1 = src[lane + 32];
    size_t base = (((size_t)(b * HH + h)) * SS + s) * HD;
    __nv_bfloat16 h0 = __float2bfloat16_rn(x0);
    __nv_bfloat16 h1 = __float2bfloat16_rn(x1);
    hi[base + lane]      = h0;
    hi[base + lane + 32] = h1;
    lo[base + lane]      = __float2bfloat16_rn(x0 - __bfloat162float(h0));
    lo[base + lane + 32] = __float2bfloat16_rn(x1 - __bfloat162float(h1));
}

// ============================================================
// Fused softmax + ctx. attn holds exp-values on entry.
// Per block: one (bh, 128-q strip).
// Phase 1: row sums -> inv (strip becomes L2-hot).
// Phase 2: p = e*inv; write final fp32 attn; convert bf16 hi/lo in regs;
//          STS -> proven ctx MMA loop (V via cp.async double buffer).
// ============================================================
__global__ __launch_bounds__(256) void smctx_kernel(
    float* __restrict__ attn,
    const __nv_bfloat16* __restrict__ Vh, const __nv_bfloat16* __restrict__ Vl,
    float* __restrict__ ctx)
{
    __shared__ __align__(16) __nv_bfloat16 sA[2][2][128 * 16];  // P bf16 hi/lo
    __shared__ __align__(16) __nv_bfloat16 sB[2][2][16 * 64];   // V hi/lo
    __shared__ float sinv[128];
    int tid = threadIdx.x, lane = tid & 31, w = tid >> 5;
    int wm = w >> 2, wn = w & 3;            // 2m x 4n; warp tile 64x16
    int bh = blockIdx.y, b = bh >> 4, h = bh & 15;
    int q0 = blockIdx.x * 128;
    float* Pa = attn + ((size_t)bh * SS + q0) * SS;
    const __nv_bfloat16* Vha = Vh + (size_t)bh * SS * HD;
    const __nv_bfloat16* Vla = Vl + (size_t)bh * SS * HD;

    uint32_t saH[2] = { smem_u32(sA[0][0]), smem_u32(sA[1][0]) };
    uint32_t saL[2] = { smem_u32(sA[0][1]), smem_u32(sA[1][1]) };
    uint32_t sbH[2] = { smem_u32(sB[0][0]), smem_u32(sB[1][0]) };
    uint32_t sbL[2] = { smem_u32(sB[0][1]), smem_u32(sB[1][1]) };

    // V loader indices + prologue issue (overlaps with phase 1)
    int bsp = tid >> 7, bk = (tid >> 3) & 15, bch = tid & 7;
    uint32_t boff = swzB(bk, bch);
    {
        size_t gb = (size_t)bk * HD + bch * 8;
        cp16((bsp ? sbL[0] : sbH[0]) + boff, (bsp ? Vla : Vha) + gb);
    }
    CP_COMMIT();

    // ---- Phase 1: per-row sum of exp values (streams strip -> L2) ----
#pragma unroll 1
    for (int i = 0; i < 16; i++) {
        int row = w * 16 + i;
        const float4* r4 = (const float4*)(Pa + (size_t)row * SS);
        float s = 0.0f;
#pragma unroll
        for (int j = 0; j < 16; j++) {
            float4 v = r4[lane + j * 32];
            s += (v.x + v.y) + (v.z + v.w);
        }
#pragma unroll
        for (int o = 16; o > 0; o >>= 1) s += __shfl_xor_sync(0xffffffffu, s, o);
        if (lane == 0) sinv[row] = 1.0f / s;
    }
    __syncthreads();

    // ---- Phase 2: scale, write attn, convert, MMA ----
    int arow = tid >> 1, ach = tid & 1;              // A: 128 rows x 2 chunks of 8
    uint32_t aoff = swz_off(arow, ach);
    float rinv = sinv[arow];
    float* Par = Pa + (size_t)arow * SS + ach * 8;

    float c[4][2][4];
#pragma unroll
    for (int i = 0; i < 4; i++)
#pragma unroll
        for (int j = 0; j < 2; j++)
#pragma unroll
            for (int k = 0; k < 4; k++) c[i][j][k] = 0.0f;

    // reg double-buffer for fp32 P (L2-hot after phase 1)
    float pv[2][8];
    *(float4*)&pv[0][0] = *(const float4*)(Par);
    *(float4*)&pv[0][4] = *(const float4*)(Par + 4);

    const int NK = SS / 16;  // 128
#pragma unroll 1
    for (int ks = 0; ks < NK; ks++) {
        int stg = ks & 1;
        // scale + write final attn + convert + STS into sA[stg]
        {
            const float* e = pv[stg];
            float p[8];
#pragma unroll
            for (int j = 0; j < 8; j++) p[j] = e[j] * rinv;
            float4 w0 = { p[0], p[1], p[2], p[3] };
            float4 w1 = { p[4], p[5], p[6], p[7] };
            *(float4*)(Par + ks * 16)     = w0;
            *(float4*)(Par + ks * 16 + 4) = w1;
            uint32_t hr[4], lr[4];
#pragma unroll
            for (int j = 0; j < 4; j++) {
                float x = p[2*j], y = p[2*j+1];
                __nv_bfloat16 hx = __float2bfloat16_rn(x);
                __nv_bfloat16 hy = __float2bfloat16_rn(y);
                __nv_bfloat162 hp; hp.x = hx; hp.y = hy;
                hr[j] = *(uint32_t*)&hp;
                lr[j] = bf2pack(x - __bfloat162float(hx), y - __bfloat162float(hy));
            }
            asm volatile("st.shared.v4.b32 [%0], {%1,%2,%3,%4};"
                :: "r"(saH[stg] + aoff), "r"(hr[0]), "r"(hr[1]), "r"(hr[2]), "r"(hr[3]) : "memory");
            asm volatile("st.shared.v4.b32 [%0], {%1,%2,%3,%4};"
                :: "r"(saL[stg] + aoff), "r"(lr[0]), "r"(lr[1]), "r"(lr[2]), "r"(lr[3]) : "memory");
        }
        if (ks + 1 < NK) {
            // prefetch fp32 tile ks+1 (L2 hit) into other reg buffer
            const float* src = Par + (ks + 1) * 16;
            *(float4*)&pv[stg ^ 1][0] = *(const float4*)(src);
            *(float4*)&pv[stg ^ 1][4] = *(const float4*)(src + 4);
            // V tile ks+1 -> stage stg^1
            size_t gb = (size_t)((ks + 1) * 16 + bk) * HD + bch * 8;
            cp16((bsp ? sbL[stg ^ 1] : sbH[stg ^ 1]) + boff, (bsp ? Vla : Vha) + gb);
            CP_COMMIT();
            CP_WAIT(1);
        } else {
            CP_WAIT(0);
        }
        __syncthreads();

        uint32_t ah[4][4], al[4][4], bhf[2][2], blf[2][2];
        int r = lane & 15, kc = lane >> 4;
#pragma unroll
        for (int fm = 0; fm < 4; fm++) {
            int row = wm * 64 + fm * 16 + r;
            uint32_t off = swz_off(row, kc);
            ldsm4(ah[fm], saH[stg] + off);
            ldsm4(al[fm], saL[stg] + off);
        }
        int rb = lane & 15;  // k rows 0..15
#pragma unroll
        for (int fn = 0; fn < 2; fn++) {
            uint32_t off = swzB(rb, wn * 2 + fn);
            ldsm2t(bhf[fn], sbH[stg] + off);   // V is [k][n]: trans
            ldsm2t(blf[fn], sbL[stg] + off);
        }
#pragma unroll
        for (int fm = 0; fm < 4; fm++)
#pragma unroll
            for (int fn = 0; fn < 2; fn++) {
                mma_bf16(c[fm][fn], ah[fm], bhf[fn]);
                mma_bf16(c[fm][fn], al[fm], bhf[fn]);
                mma_bf16(c[fm][fn], ah[fm], blf[fn]);
            }
        __syncthreads();
    }

    int r0 = lane >> 2, cc = (lane & 3) << 1;
#pragma unroll
    for (int fn = 0; fn < 2; fn++) {
        int col = wn * 16 + fn * 8 + cc;       // 0..63
#pragma unroll
        for (int fm = 0; fm < 4; fm++) {
            int gq = q0 + wm * 64 + fm * 16 + r0;
            float2 v0 = { c[fm][fn][0], c[fm][fn][1] };
            float2 v1 = { c[fm][fn][2], c[fm][fn][3] };
            *(float2*)(ctx + ((size_t)b * SS + gq) * DD + h * HD + col) = v0;
            *(float2*)(ctx + ((size_t)b * SS + gq + 8) * DD + h * HD + col) = v1;
        }
    }
}

// ============================================================
extern "C" void kernel_launch(void* const* d_in, const int* in_sizes, int n_in,
                              void* d_out, int out_size)
{
    const float* query = (const float*)d_in[0];
    const float* key   = (const float*)d_in[1];
    const float* value = (const float*)d_in[2];
    const int*   mask  = (const int*)  d_in[3];
    const float* Wq = (const float*)d_in[4];  const float* bq = (const float*)d_in[5];
    const float* Wk = (const float*)d_in[6];  const float* bk = (const float*)d_in[7];
    const float* Wv = (const float*)d_in[8];  const float* bv = (const float*)d_in[9];
    const float* Wo = (const float*)d_in[10]; const float* bo = (const float*)d_in[11];
    const float* scale = (const float*)d_in[12];

    float* out = (float*)d_out;
    const size_t CTX_ELEMS  = (size_t)MTOK * DD;
    const size_t ATTN_ELEMS = (size_t)BHN * SS * SS;

    float *tmp, *ctx, *attn_scratch;
    __nv_bfloat16 *Ahi, *Alo, *Whi, *Wlo, *Qh, *Ql, *Kh, *Kl, *Vh, *Vl;
    cudaGetSymbolAddress((void**)&tmp,  g_tmp);
    cudaGetSymbolAddress((void**)&ctx,  g_ctx);
    cudaGetSymbolAddress((void**)&attn_scratch, g_attn);
    cudaGetSymbolAddress((void**)&Ahi,  g_Ahi);
    cudaGetSymbolAddress((void**)&Alo,  g_Alo);
    cudaGetSymbolAddress((void**)&Whi,  g_Whi);
    cudaGetSymbolAddress((void**)&Wlo,  g_Wlo);
    cudaGetSymbolAddress((void**)&Qh,   g_Qh);
    cudaGetSymbolAddress((void**)&Ql,   g_Ql);
    cudaGetSymbolAddress((void**)&Kh,   g_Kh);
    cudaGetSymbolAddress((void**)&Kl,   g_Kl);
    cudaGetSymbolAddress((void**)&Vh,   g_Vh);
    cudaGetSymbolAddress((void**)&Vl,   g_Vl);

    float* attn = ((size_t)out_size >= CTX_ELEMS + ATTN_ELEMS) ? (out + CTX_ELEMS)
                                                               : attn_scratch;

    const int A4 = MTOK * DD / 4;   // 1M float4
    const int W4 = DD * DD / 4;     // 256K float4
    dim3 gProj(DD / 128, MTOK / 128);           // (8, 32)
    dim3 gNorm(MTOK * HH / 8);                  // 8192
    dim3 gScore(SS / 128, SS / 128, BHN);       // (16, 16, 32)
    dim3 gCtx(SS / 128, BHN);                   // (16, 32)

    // --- Q projection ---
    cvt_split_kernel<<<(A4+255)/256, 256>>>((const float4*)query, (uint2*)Ahi, (uint2*)Alo, A4);
    cvt_split_kernel<<<(W4+255)/256, 256>>>((const float4*)Wq, (uint2*)Whi, (uint2*)Wlo, W4);
    gemm_bf16s_kernel<<<gProj, 256>>>(Ahi, Alo, Whi, Wlo, bq, tmp, MTOK, DD, DD);
    norm_split_bf16_kernel<<<gNorm, 256>>>(tmp, Qh, Ql);
    // --- K projection ---
    cvt_split_kernel<<<(A4+255)/256, 256>>>((const float4*)key, (uint2*)Ahi, (uint2*)Alo, A4);
    cvt_split_kernel<<<(W4+255)/256, 256>>>((const float4*)Wk, (uint2*)Whi, (uint2*)Wlo, W4);
    gemm_bf16s_kernel<<<gProj, 256>>>(Ahi, Alo, Whi, Wlo, bk, tmp, MTOK, DD, DD);
    norm_split_bf16_kernel<<<gNorm, 256>>>(tmp, Kh, Kl);
    // --- V projection ---
    cvt_split_kernel<<<(A4+255)/256, 256>>>((const float4*)value, (uint2*)Ahi, (uint2*)Alo, A4);
    cvt_split_kernel<<<(W4+255)/256, 256>>>((const float4*)Wv, (uint2*)Whi, (uint2*)Wlo, W4);
    gemm_bf16s_kernel<<<gProj, 256>>>(Ahi, Alo, Whi, Wlo, bv, tmp, MTOK, DD, DD);
    split_v_bf16_kernel<<<gNorm, 256>>>(tmp, Vh, Vl);

    // --- attention: scores write exp(x); fused softmax+ctx finishes ---
    scores_mma_kernel<<<gScore, 256>>>(Qh, Ql, Kh, Kl, mask, scale, attn);
    smctx_kernel<<<gCtx, 256>>>(attn, Vh, Vl, ctx);

    // --- output projection ---
    cvt_split_kernel<<<(A4+255)/256, 256>>>((const float4*)ctx, (uint2*)Ahi, (uint2*)Alo, A4);
    cvt_split_kernel<<<(W4+255)/256, 256>>>((const float4*)Wo, (uint2*)Whi, (uint2*)Wlo, W4);
    gemm_bf16s_kernel<<<gProj, 256>>>(Ahi, Alo, Whi, Wlo, bo, out, MTOK, DD, DD);
}

// round 17
// speedup vs baseline: 1.2092x; 1.2092x over previous
#include <cuda_runtime.h>
#include <cuda_bf16.h>
#include <cuda_fp16.h>
#include <math.h>
#include <stdint.h>

#define BB   2
#define SS   2048
#define DD   1024
#define HH   16
#define HD   64
#define BHN  (BB*HH)       // 32
#define MTOK (BB*SS)       // 4096

// ---- static scratch (allocation-free rule: __device__ globals) ----
__device__ float g_tmp[(size_t)MTOK*DD];          // projection temp [B,S,D]
__device__ float g_ctx[(size_t)MTOK*DD];          // merged-head context
__device__ float g_attn[(size_t)BHN*SS*SS];       // fallback attn
__device__ __nv_bfloat16 g_Ahi[(size_t)MTOK*DD];  // activation split
__device__ __nv_bfloat16 g_Alo[(size_t)MTOK*DD];
__device__ __nv_bfloat16 g_Whi[(size_t)DD*DD];    // weight split
__device__ __nv_bfloat16 g_Wlo[(size_t)DD*DD];
__device__ __nv_bfloat16 g_Qh[(size_t)BHN*SS*HD]; // normalized Q/K split
__device__ __nv_bfloat16 g_Ql[(size_t)BHN*SS*HD];
__device__ __nv_bfloat16 g_Kh[(size_t)BHN*SS*HD];
__device__ __nv_bfloat16 g_Kl[(size_t)BHN*SS*HD];
__device__ __half g_Vh[(size_t)BHN*SS*HD];        // V split heads fp16 hi/lo
__device__ __half g_Vl[(size_t)BHN*SS*HD];
__device__ __half g_Pf[(size_t)BHN*SS*SS];        // softmax probs, single fp16

// ============================================================
// helpers
// ============================================================
__device__ __forceinline__ uint32_t smem_u32(const void* p) {
    return (uint32_t)__cvta_generic_to_shared(p);
}
__device__ __forceinline__ void cp16(uint32_t dst, const void* src) {
    asm volatile("cp.async.ca.shared.global [%0], [%1], 16;" :: "r"(dst), "l"(src));
}
#define CP_COMMIT() asm volatile("cp.async.commit_group;")
#define CP_WAIT(n)  asm volatile("cp.async.wait_group %0;" :: "n"(n))

__device__ __forceinline__ void ldsm4(uint32_t* r, uint32_t a) {
    asm volatile("ldmatrix.sync.aligned.m8n8.x4.shared.b16 {%0,%1,%2,%3}, [%4];"
        : "=r"(r[0]), "=r"(r[1]), "=r"(r[2]), "=r"(r[3]) : "r"(a));
}
// non-transposed x2: B stored [n][k] (contiguous k) for mma.row.col
__device__ __forceinline__ void ldsm2(uint32_t* r, uint32_t a) {
    asm volatile("ldmatrix.sync.aligned.m8n8.x2.shared.b16 {%0,%1}, [%2];"
        : "=r"(r[0]), "=r"(r[1]) : "r"(a));
}
// transposed x2: B stored [k][n] (contiguous n)
__device__ __forceinline__ void ldsm2t(uint32_t* r, uint32_t a) {
    asm volatile("ldmatrix.sync.aligned.m8n8.x2.trans.shared.b16 {%0,%1}, [%2];"
        : "=r"(r[0]), "=r"(r[1]) : "r"(a));
}
__device__ __forceinline__ void mma_bf16(float* c, const uint32_t* a, const uint32_t* b) {
    asm volatile(
        "mma.sync.aligned.m16n8k16.row.col.f32.bf16.bf16.f32 "
        "{%0,%1,%2,%3}, {%4,%5,%6,%7}, {%8,%9}, {%0,%1,%2,%3};"
        : "+f"(c[0]), "+f"(c[1]), "+f"(c[2]), "+f"(c[3])
        : "r"(a[0]), "r"(a[1]), "r"(a[2]), "r"(a[3]), "r"(b[0]), "r"(b[1]));
}
__device__ __forceinline__ void mma_f16(float* c, const uint32_t* a, const uint32_t* b) {
    asm volatile(
        "mma.sync.aligned.m16n8k16.row.col.f32.f16.f16.f32 "
        "{%0,%1,%2,%3}, {%4,%5,%6,%7}, {%8,%9}, {%0,%1,%2,%3};"
        : "+f"(c[0]), "+f"(c[1]), "+f"(c[2]), "+f"(c[3])
        : "r"(a[0]), "r"(a[1]), "r"(a[2]), "r"(a[3]), "r"(b[0]), "r"(b[1]));
}

// swizzled smem offset for [row][chunk-of-16B] tiles (row stride 32B)
__device__ __forceinline__ uint32_t swz_off(int row, int chunk) {
    return (uint32_t)(row * 32 + ((chunk ^ ((row >> 2) & 1)) << 4));
}
// swizzled offset for 128B-row tiles: [k-row][8 chunks of 16B]
__device__ __forceinline__ uint32_t swzB(int k, int chunk) {
    return (uint32_t)(k * 128 + ((chunk ^ (k & 7)) << 4));
}

__device__ __forceinline__ uint32_t bf2pack(float a, float b) {
    __nv_bfloat162 t;
    t.x = __float2bfloat16_rn(a);
    t.y = __float2bfloat16_rn(b);
    return *(uint32_t*)&t;
}

// ============================================================
// fp32 -> bf16 hi/lo split
// ============================================================
__global__ __launch_bounds__(256) void cvt_split_kernel(
    const float4* __restrict__ x, uint2* __restrict__ hi, uint2* __restrict__ lo, int n4)
{
    int i = blockIdx.x * 256 + threadIdx.x;
    if (i >= n4) return;
    float4 v = x[i];
    __nv_bfloat16 hx = __float2bfloat16_rn(v.x);
    __nv_bfloat16 hy = __float2bfloat16_rn(v.y);
    __nv_bfloat16 hz = __float2bfloat16_rn(v.z);
    __nv_bfloat16 hw = __float2bfloat16_rn(v.w);
    uint2 h, l;
    { __nv_bfloat162 t; t.x = hx; t.y = hy; h.x = *(uint32_t*)&t; }
    { __nv_bfloat162 t; t.x = hz; t.y = hw; h.y = *(uint32_t*)&t; }
    l.x = bf2pack(v.x - __bfloat162float(hx), v.y - __bfloat162float(hy));
    l.y = bf2pack(v.z - __bfloat162float(hz), v.w - __bfloat162float(hw));
    hi[i] = h;
    lo[i] = l;
}

// ============================================================
// shared GEMM machinery: 128x128 tile, 8 warps (2m x 4n), k-step 16
// ============================================================
__device__ __forceinline__ void load_stage(
    uint32_t saH, uint32_t saL, uint32_t sbH, uint32_t sbL,
    const __nv_bfloat16* Ah, const __nv_bfloat16* Al,
    const __nv_bfloat16* Bh, const __nv_bfloat16* Bl,
    int K, int k0, int tid)
{
    int row = tid >> 1, ch = tid & 1;
    uint32_t off = swz_off(row, ch);
    size_t g = (size_t)row * K + k0 + ch * 8;
    cp16(saH + off, Ah + g);
    cp16(saL + off, Al + g);
    cp16(sbH + off, Bh + g);
    cp16(sbL + off, Bl + g);
}

__device__ __forceinline__ void compute_step(
    uint32_t saH, uint32_t saL, uint32_t sbH, uint32_t sbL,
    int wm, int wn, int lane, float c[4][4][4])
{
    uint32_t ah[4][4], al[4][4], bh[4][2], bl[4][2];
    int r = lane & 15, kc = lane >> 4;
#pragma unroll
    for (int fm = 0; fm < 4; fm++) {
        int row = wm * 64 + fm * 16 + r;
        uint32_t off = swz_off(row, kc);
        ldsm4(ah[fm], saH + off);
        ldsm4(al[fm], saL + off);
    }
    int rb = lane & 7, kb = (lane >> 3) & 1;
#pragma unroll
    for (int fn = 0; fn < 4; fn++) {
        int row = wn * 32 + fn * 8 + rb;
        uint32_t off = swz_off(row, kb);
        ldsm2(bh[fn], sbH + off);   // B is [n][k]: NON-trans
        ldsm2(bl[fn], sbL + off);
    }
#pragma unroll
    for (int fm = 0; fm < 4; fm++)
#pragma unroll
        for (int fn = 0; fn < 4; fn++) {
            mma_bf16(c[fm][fn], ah[fm], bh[fn]);
            mma_bf16(c[fm][fn], ah[fm], bl[fn]);
            mma_bf16(c[fm][fn], al[fm], bh[fn]);
        }
}

// ============================================================
// projection GEMM: C[M,N] = A@W^T + bias (bf16-split inputs)
// ============================================================
__global__ __launch_bounds__(256) void gemm_bf16s_kernel(
    const __nv_bfloat16* __restrict__ Ah, const __nv_bfloat16* __restrict__ Al,
    const __nv_bfloat16* __restrict__ Wh, const __nv_bfloat16* __restrict__ Wl,
    const float* __restrict__ bias, float* __restrict__ C, int M, int N, int K)
{
    __shared__ __align__(16) __nv_bfloat16 sA[2][2][128 * 16];
    __shared__ __align__(16) __nv_bfloat16 sB[2][2][128 * 16];
    int tid = threadIdx.x, lane = tid & 31, w = tid >> 5;
    int wm = w >> 2, wn = w & 3;
    int m0 = blockIdx.y * 128, n0 = blockIdx.x * 128;
    const __nv_bfloat16* Ah_b = Ah + (size_t)m0 * K;
    const __nv_bfloat16* Al_b = Al + (size_t)m0 * K;
    const __nv_bfloat16* Wh_b = Wh + (size_t)n0 * K;
    const __nv_bfloat16* Wl_b = Wl + (size_t)n0 * K;

    uint32_t saH[2] = { smem_u32(sA[0][0]), smem_u32(sA[1][0]) };
    uint32_t saL[2] = { smem_u32(sA[0][1]), smem_u32(sA[1][1]) };
    uint32_t sbH[2] = { smem_u32(sB[0][0]), smem_u32(sB[1][0]) };
    uint32_t sbL[2] = { smem_u32(sB[0][1]), smem_u32(sB[1][1]) };

    float c[4][4][4];
#pragma unroll
    for (int i = 0; i < 4; i++)
#pragma unroll
        for (int j = 0; j < 4; j++)
#pragma unroll
            for (int k = 0; k < 4; k++) c[i][j][k] = 0.0f;

    const int NK = K / 16;
    load_stage(saH[0], saL[0], sbH[0], sbL[0], Ah_b, Al_b, Wh_b, Wl_b, K, 0, tid);
    CP_COMMIT();

#pragma unroll 1
    for (int ks = 0; ks < NK; ks++) {
        int stg = ks & 1;
        if (ks + 1 < NK) {
            load_stage(saH[stg ^ 1], saL[stg ^ 1], sbH[stg ^ 1], sbL[stg ^ 1],
                       Ah_b, Al_b, Wh_b, Wl_b, K, (ks + 1) * 16, tid);
            CP_COMMIT();
            CP_WAIT(1);
        } else {
            CP_WAIT(0);
        }
        __syncthreads();
        compute_step(saH[stg], saL[stg], sbH[stg], sbL[stg], wm, wn, lane, c);
        __syncthreads();
    }

    int r0 = lane >> 2, cc = (lane & 3) << 1;
#pragma unroll
    for (int fn = 0; fn < 4; fn++) {
        int gcol = n0 + wn * 32 + fn * 8 + cc;
        float2 bb = *(const float2*)(bias + gcol);
#pragma unroll
        for (int fm = 0; fm < 4; fm++) {
            int gr = m0 + wm * 64 + fm * 16 + r0;
            float2 v0 = { c[fm][fn][0] + bb.x, c[fm][fn][1] + bb.y };
            float2 v1 = { c[fm][fn][2] + bb.x, c[fm][fn][3] + bb.y };
            *(float2*)(C + (size_t)gr * N + gcol) = v0;
            *(float2*)(C + (size_t)(gr + 8) * N + gcol) = v1;
        }
    }
}

// ============================================================
// scores GEMM: attn = mask? scale*Qn@Kn^T : -1e9, per (b,h)
// ============================================================
__global__ __launch_bounds__(256) void scores_mma_kernel(
    const __nv_bfloat16* __restrict__ Qh, const __nv_bfloat16* __restrict__ Ql,
    const __nv_bfloat16* __restrict__ Kh, const __nv_bfloat16* __restrict__ Kl,
    const int* __restrict__ mask, const float* __restrict__ scale_p,
    float* __restrict__ attn)
{
    __shared__ __align__(16) __nv_bfloat16 sA[2][2][128 * 16];
    __shared__ __align__(16) __nv_bfloat16 sB[2][2][128 * 16];
    __shared__ int smask[128];
    int tid = threadIdx.x, lane = tid & 31, w = tid >> 5;
    int wm = w >> 2, wn = w & 3;
    int bh = blockIdx.z, b = bh >> 4;
    int q0 = blockIdx.y * 128, k0g = blockIdx.x * 128;
    const __nv_bfloat16* Ah_b = Qh + ((size_t)bh * SS + q0) * HD;
    const __nv_bfloat16* Al_b = Ql + ((size_t)bh * SS + q0) * HD;
    const __nv_bfloat16* Bh_b = Kh + ((size_t)bh * SS + k0g) * HD;
    const __nv_bfloat16* Bl_b = Kl + ((size_t)bh * SS + k0g) * HD;

    if (tid < 128) smask[tid] = mask[b * SS + k0g + tid];

    uint32_t saH[2] = { smem_u32(sA[0][0]), smem_u32(sA[1][0]) };
    uint32_t saL[2] = { smem_u32(sA[0][1]), smem_u32(sA[1][1]) };
    uint32_t sbH[2] = { smem_u32(sB[0][0]), smem_u32(sB[1][0]) };
    uint32_t sbL[2] = { smem_u32(sB[0][1]), smem_u32(sB[1][1]) };

    float c[4][4][4];
#pragma unroll
    for (int i = 0; i < 4; i++)
#pragma unroll
        for (int j = 0; j < 4; j++)
#pragma unroll
            for (int k = 0; k < 4; k++) c[i][j][k] = 0.0f;

    const int NK = HD / 16;  // 4
    load_stage(saH[0], saL[0], sbH[0], sbL[0], Ah_b, Al_b, Bh_b, Bl_b, HD, 0, tid);
    CP_COMMIT();

#pragma unroll 1
    for (int ks = 0; ks < NK; ks++) {
        int stg = ks & 1;
        if (ks + 1 < NK) {
            load_stage(saH[stg ^ 1], saL[stg ^ 1], sbH[stg ^ 1], sbL[stg ^ 1],
                       Ah_b, Al_b, Bh_b, Bl_b, HD, (ks + 1) * 16, tid);
            CP_COMMIT();
            CP_WAIT(1);
        } else {
            CP_WAIT(0);
        }
        __syncthreads();
        compute_step(saH[stg], saL[stg], sbH[stg], sbL[stg], wm, wn, lane, c);
        __syncthreads();
    }

    float scl = __ldg(scale_p);
    int r0 = lane >> 2, cc = (lane & 3) << 1;
#pragma unroll
    for (int fn = 0; fn < 4; fn++) {
        int lcol = wn * 32 + fn * 8 + cc;
        int m0v = smask[lcol], m1v = smask[lcol + 1];
        int gcol = k0g + lcol;
#pragma unroll
        for (int fm = 0; fm < 4; fm++) {
            int gq = q0 + wm * 64 + fm * 16 + r0;
            float2 v0, v1;
            v0.x = m0v ? scl * c[fm][fn][0] : -1e9f;
            v0.y = m1v ? scl * c[fm][fn][1] : -1e9f;
            v1.x = m0v ? scl * c[fm][fn][2] : -1e9f;
            v1.y = m1v ? scl * c[fm][fn][3] : -1e9f;
            *(float2*)(attn + ((size_t)bh * SS + gq) * SS + gcol) = v0;
            *(float2*)(attn + ((size_t)bh * SS + gq + 8) * SS + gcol) = v1;
        }
    }
}

// ============================================================
// Center-normalize + split into bf16 hi/lo [B,H,S,64]
// ============================================================
__global__ __launch_bounds__(256) void norm_split_bf16_kernel(
    const float* __restrict__ Y, __nv_bfloat16* __restrict__ hi,
    __nv_bfloat16* __restrict__ lo)
{
    int gw   = blockIdx.x * 8 + (threadIdx.x >> 5);
    int lane = threadIdx.x & 31;
    int h = gw & 15;
    int s = (gw >> 4) & (SS - 1);
    int b = gw >> 15;
    const float* src = Y + ((size_t)(b * SS + s)) * DD + h * HD;
    float x0 = src[lane], x1 = src[lane + 32];
    float sum = x0 + x1;
#pragma unroll
    for (int o = 16; o > 0; o >>= 1) sum += __shfl_xor_sync(0xffffffffu, sum, o);
    float mean = sum * (1.0f / 64.0f);
    x0 -= mean; x1 -= mean;
    float ss = x0 * x0 + x1 * x1;
#pragma unroll
    for (int o = 16; o > 0; o >>= 1) ss += __shfl_xor_sync(0xffffffffu, ss, o);
    float inv = 1.0f / fmaxf(sqrtf(ss), 1e-12f);
    x0 *= inv; x1 *= inv;
    size_t base = (((size_t)(b * HH + h)) * SS + s) * HD;
    __nv_bfloat16 h0 = __float2bfloat16_rn(x0);
    __nv_bfloat16 h1 = __float2bfloat16_rn(x1);
    hi[base + lane]      = h0;
    hi[base + lane + 32] = h1;
    lo[base + lane]      = __float2bfloat16_rn(x0 - __bfloat162float(h0));
    lo[base + lane + 32] = __float2bfloat16_rn(x1 - __bfloat162float(h1));
}

// V path: split heads + fp16 hi/lo split
__global__ __launch_bounds__(256) void split_v_fp16_kernel(
    const float* __restrict__ Y, __half* __restrict__ hi,
    __half* __restrict__ lo)
{
    int gw   = blockIdx.x * 8 + (threadIdx.x >> 5);
    int lane = threadIdx.x & 31;
    int h = gw & 15;
    int s = (gw >> 4) & (SS - 1);
    int b = gw >> 15;
    const float* src = Y + ((size_t)(b * SS + s)) * DD + h * HD;
    float x0 = src[lane], x1 = src[lane + 32];
    size_t base = (((size_t)(b * HH + h)) * SS + s) * HD;
    __half h0 = __float2half_rn(x0);
    __half h1 = __float2half_rn(x1);
    hi[base + lane]      = h0;
    hi[base + lane + 32] = h1;
    lo[base + lane]      = __float2half_rn(x0 - __half2float(h0));
    lo[base + lane + 32] = __float2half_rn(x1 - __half2float(h1));
}

// ============================================================
// In-place row softmax over last dim (2048), also emits single fp16 P.
// ============================================================
__global__ __launch_bounds__(256) void softmax_kernel(
    float* __restrict__ attn, __half* __restrict__ pf)
{
    __shared__ float red[8];
    size_t rowoff = (size_t)blockIdx.x * SS;
    float* p = attn + rowoff;
    int tid = threadIdx.x, lane = tid & 31, wid = tid >> 5;
    float v[8];
    float m = -3.402823466e38f;
#pragma unroll
    for (int i = 0; i < 8; i++) { v[i] = p[tid + i*256]; m = fmaxf(m, v[i]); }
#pragma unroll
    for (int o = 16; o > 0; o >>= 1) m = fmaxf(m, __shfl_xor_sync(0xffffffffu, m, o));
    if (lane == 0) red[wid] = m;
    __syncthreads();
    float mm = red[0];
#pragma unroll
    for (int w = 1; w < 8; w++) mm = fmaxf(mm, red[w]);

    float s = 0.0f;
#pragma unroll
    for (int i = 0; i < 8; i++) { v[i] = __expf(v[i] - mm); s += v[i]; }
#pragma unroll
    for (int o = 16; o > 0; o >>= 1) s += __shfl_xor_sync(0xffffffffu, s, o);
    __syncthreads();
    if (lane == 0) red[wid] = s;
    __syncthreads();
    float tot = red[0]+red[1]+red[2]+red[3]+red[4]+red[5]+red[6]+red[7];
    float inv = 1.0f / tot;
#pragma unroll
    for (int i = 0; i < 8; i++) {
        int idx = tid + i*256;
        float r = v[i] * inv;
        p[idx] = r;
        pf[rowoff + idx] = __float2half_rn(r);
    }
}

// ============================================================
// ctx = P @ V, P single fp16, V fp16 hi/lo: c += P*Vh + P*Vl.
// Per (b,h): M=128 q-tile, N=64, K=2048.
// P tiles [q][k] like A; V tiles [k][n] -> trans B loads.
// ============================================================
__global__ __launch_bounds__(256) void ctx_mma_kernel(
    const __half* __restrict__ Pf,
    const __half* __restrict__ Vh, const __half* __restrict__ Vl,
    float* __restrict__ ctx)
{
    __shared__ __align__(16) __half sA[2][128 * 16];   // P fp16, 4KB/stage
    __shared__ __align__(16) __half sB[2][2][16 * 64]; // V hi/lo
    int tid = threadIdx.x, lane = tid & 31, w = tid >> 5;
    int wm = w >> 2, wn = w & 3;            // 2m x 4n; warp tile 64x16
    int bh = blockIdx.y, b = bh >> 4, h = bh & 15;
    int q0 = blockIdx.x * 128;
    const __half* Pa = Pf + ((size_t)bh * SS + q0) * SS;
    const __half* Vha = Vh + (size_t)bh * SS * HD;
    const __half* Vla = Vl + (size_t)bh * SS * HD;

    uint32_t sa[2]  = { smem_u32(sA[0]), smem_u32(sA[1]) };
    uint32_t sbH[2] = { smem_u32(sB[0][0]), smem_u32(sB[1][0]) };
    uint32_t sbL[2] = { smem_u32(sB[0][1]), smem_u32(sB[1][1]) };

    // loader indices
    int arow = tid >> 1, ach = tid & 1;              // A: 128 rows x 2 chunks
    int bsp = tid >> 7, bk = (tid >> 3) & 15, bch = tid & 7;
    uint32_t aoff = swz_off(arow, ach);
    uint32_t boff = swzB(bk, bch);

    float c[4][2][4];
#pragma unroll
    for (int i = 0; i < 4; i++)
#pragma unroll
        for (int j = 0; j < 2; j++)
#pragma unroll
            for (int k = 0; k < 4; k++) c[i][j][k] = 0.0f;

    // prologue load k0=0
    {
        size_t ga = (size_t)arow * SS + ach * 8;
        cp16(sa[0] + aoff, Pa + ga);
        size_t gb = (size_t)bk * HD + bch * 8;
        cp16((bsp ? sbL[0] : sbH[0]) + boff, (bsp ? Vla : Vha) + gb);
    }
    CP_COMMIT();

    const int NK = SS / 16;  // 128
#pragma unroll 1
    for (int ks = 0; ks < NK; ks++) {
        int stg = ks & 1;
        if (ks + 1 < NK) {
            int k0 = (ks + 1) * 16;
            size_t ga = (size_t)arow * SS + k0 + ach * 8;
            cp16(sa[stg ^ 1] + aoff, Pa + ga);
            size_t gb = (size_t)(k0 + bk) * HD + bch * 8;
            cp16((bsp ? sbL[stg ^ 1] : sbH[stg ^ 1]) + boff, (bsp ? Vla : Vha) + gb);
            CP_COMMIT();
            CP_WAIT(1);
        } else {
            CP_WAIT(0);
        }
        __syncthreads();

        uint32_t ap[4][4], bhf[2][2], blf[2][2];
        int r = lane & 15, kc = lane >> 4;
#pragma unroll
        for (int fm = 0; fm < 4; fm++) {
            int row = wm * 64 + fm * 16 + r;
            uint32_t off = swz_off(row, kc);
            ldsm4(ap[fm], sa[stg] + off);
        }
        int rb = lane & 15;  // k rows 0..15
#pragma unroll
        for (int fn = 0; fn < 2; fn++) {
            uint32_t off = swzB(rb, wn * 2 + fn);
            ldsm2t(bhf[fn], sbH[stg] + off);   // V is [k][n]: trans
            ldsm2t(blf[fn], sbL[stg] + off);
        }
#pragma unroll
        for (int fm = 0; fm < 4; fm++)
#pragma unroll
            for (int fn = 0; fn < 2; fn++) {
                mma_f16(c[fm][fn], ap[fm], bhf[fn]);
                mma_f16(c[fm][fn], ap[fm], blf[fn]);
            }
        __syncthreads();
    }

    int r0 = lane >> 2, cc = (lane & 3) << 1;
#pragma unroll
    for (int fn = 0; fn < 2; fn++) {
        int col = wn * 16 + fn * 8 + cc;       // 0..63
#pragma unroll
        for (int fm = 0; fm < 4; fm++) {
            int gq = q0 + wm * 64 + fm * 16 + r0;
            float2 v0 = { c[fm][fn][0], c[fm][fn][1] };
            float2 v1 = { c[fm][fn][2], c[fm][fn][3] };
            *(float2*)(ctx + ((size_t)b * SS + gq) * DD + h * HD + col) = v0;
            *(float2*)(ctx + ((size_t)b * SS + gq + 8) * DD + h * HD + col) = v1;
        }
    }
}

// ============================================================
extern "C" void kernel_launch(void* const* d_in, const int* in_sizes, int n_in,
                              void* d_out, int out_size)
{
    const float* query = (const float*)d_in[0];
    const float* key   = (const float*)d_in[1];
    const float* value = (const float*)d_in[2];
    const int*   mask  = (const int*)  d_in[3];
    const float* Wq = (const float*)d_in[4];  const float* bq = (const float*)d_in[5];
    const float* Wk = (const float*)d_in[6];  const float* bk = (const float*)d_in[7];
    const float* Wv = (const float*)d_in[8];  const float* bv = (const float*)d_in[9];
    const float* Wo = (const float*)d_in[10]; const float* bo = (const float*)d_in[11];
    const float* scale = (const float*)d_in[12];

    float* out = (float*)d_out;
    const size_t CTX_ELEMS  = (size_t)MTOK * DD;
    const size_t ATTN_ELEMS = (size_t)BHN * SS * SS;

    float *tmp, *ctx, *attn_scratch;
    __nv_bfloat16 *Ahi, *Alo, *Whi, *Wlo, *Qh, *Ql, *Kh, *Kl;
    __half *Vh, *Vl, *Pf;
    cudaGetSymbolAddress((void**)&tmp,  g_tmp);
    cudaGetSymbolAddress((void**)&ctx,  g_ctx);
    cudaGetSymbolAddress((void**)&attn_scratch, g_attn);
    cudaGetSymbolAddress((void**)&Ahi,  g_Ahi);
    cudaGetSymbolAddress((void**)&Alo,  g_Alo);
    cudaGetSymbolAddress((void**)&Whi,  g_Whi);
    cudaGetSymbolAddress((void**)&Wlo,  g_Wlo);
    cudaGetSymbolAddress((void**)&Qh,   g_Qh);
    cudaGetSymbolAddress((void**)&Ql,   g_Ql);
    cudaGetSymbolAddress((void**)&Kh,   g_Kh);
    cudaGetSymbolAddress((void**)&Kl,   g_Kl);
    cudaGetSymbolAddress((void**)&Vh,   g_Vh);
    cudaGetSymbolAddress((void**)&Vl,   g_Vl);
    cudaGetSymbolAddress((void**)&Pf,   g_Pf);

    float* attn = ((size_t)out_size >= CTX_ELEMS + ATTN_ELEMS) ? (out + CTX_ELEMS)
                                                               : attn_scratch;

    const int A4 = MTOK * DD / 4;   // 1M float4
    const int W4 = DD * DD / 4;     // 256K float4
    dim3 gProj(DD / 128, MTOK / 128);           // (8, 32)
    dim3 gNorm(MTOK * HH / 8);                  // 8192
    dim3 gScore(SS / 128, SS / 128, BHN);       // (16, 16, 32)
    dim3 gCtx(SS / 128, BHN);                   // (16, 32)

    // --- Q projection ---
    cvt_split_kernel<<<(A4+255)/256, 256>>>((const float4*)query, (uint2*)Ahi, (uint2*)Alo, A4);
    cvt_split_kernel<<<(W4+255)/256, 256>>>((const float4*)Wq, (uint2*)Whi, (uint2*)Wlo, W4);
    gemm_bf16s_kernel<<<gProj, 256>>>(Ahi, Alo, Whi, Wlo, bq, tmp, MTOK, DD, DD);
    norm_split_bf16_kernel<<<gNorm, 256>>>(tmp, Qh, Ql);
    // --- K projection ---
    cvt_split_kernel<<<(A4+255)/256, 256>>>((const float4*)key, (uint2*)Ahi, (uint2*)Alo, A4);
    cvt_split_kernel<<<(W4+255)/256, 256>>>((const float4*)Wk, (uint2*)Whi, (uint2*)Wlo, W4);
    gemm_bf16s_kernel<<<gProj, 256>>>(Ahi, Alo, Whi, Wlo, bk, tmp, MTOK, DD, DD);
    norm_split_bf16_kernel<<<gNorm, 256>>>(tmp, Kh, Kl);
    // --- V projection ---
    cvt_split_kernel<<<(A4+255)/256, 256>>>((const float4*)value, (uint2*)Ahi, (uint2*)Alo, A4);
    cvt_split_kernel<<<(W4+255)/256, 256>>>((const float4*)Wv, (uint2*)Whi, (uint2*)Wlo, W4);
    gemm_bf16s_kernel<<<gProj, 256>>>(Ahi, Alo, Whi, Wlo, bv, tmp, MTOK, DD, DD);
    split_v_fp16_kernel<<<gNorm, 256>>>(tmp, Vh, Vl);

    // --- attention ---
    scores_mma_kernel<<<gScore, 256>>>(Qh, Ql, Kh, Kl, mask, scale, attn);
    softmax_kernel<<<BHN * SS, 256>>>(attn, Pf);
    ctx_mma_kernel<<<gCtx, 256>>>(Pf, Vh, Vl, ctx);

    // --- output projection ---
    cvt_split_kernel<<<(A4+255)/256, 256>>>((const float4*)ctx, (uint2*)Ahi, (uint2*)Alo, A4);
    cvt_split_kernel<<<(W4+255)/256, 256>>>((const float4*)Wo, (uint2*)Whi, (uint2*)Wlo, W4);
    gemm_bf16s_kernel<<<gProj, 256>>>(Ahi, Alo, Whi, Wlo, bo, out, MTOK, DD, DD);
}